// round 1
// baseline (speedup 1.0000x reference)
#include <cuda_runtime.h>
#include <cstdint>

// Problem constants
#define NB   1024   // batch
#define CIN  64     // input channels (2 groups of 32)
#define HH   28
#define WW   28
#define LL   32     // effective channels
#define KK   288    // GEMM K = 32*3*3  (kk = l*9 + j*3 + k, matches W flattening)
#define II   128    // output channels
#define PAIRS (NB*HH)   // 28672 (n,h) pairs

#define WS_FLOATS (KK*II)          // 36864 floats = 147456 B
#define WS_BYTES  (WS_FLOATS*4)
#define T6_ELEMS  (KK*WW)          // 8064 ull (each holds duplicated f32x2)
#define T6_BYTES  (T6_ELEMS*8)     // 64512 B
#define SMEM_TOTAL (WS_BYTES + T6_BYTES)  // 211968 B

__device__ __forceinline__ unsigned long long fma2(unsigned long long a,
                                                   unsigned long long b,
                                                   unsigned long long c) {
    unsigned long long d;
    asm("fma.rn.f32x2 %0, %1, %2, %3;" : "=l"(d) : "l"(a), "l"(b), "l"(c));
    return d;
}

__device__ __forceinline__ float ull_lo(unsigned long long v) {
    return __uint_as_float((unsigned)(v & 0xffffffffull));
}
__device__ __forceinline__ float ull_hi(unsigned long long v) {
    return __uint_as_float((unsigned)(v >> 32));
}

__global__ __launch_bounds__(128, 1)
void shiftconv_kernel(const float* __restrict__ x,
                      const float* __restrict__ Wg,
                      float* __restrict__ out) {
    extern __shared__ char smem[];
    float* ws = reinterpret_cast<float*>(smem);                       // [KK][II]
    unsigned long long* t6s =
        reinterpret_cast<unsigned long long*>(smem + WS_BYTES);       // [KK][WW] dup f32x2

    const int tid = threadIdx.x;

    // ---- Phase A: stage weights into smem (verbatim copy; layout already [kk][i]) ----
    {
        const float4* src = reinterpret_cast<const float4*>(Wg);
        float4* dst = reinterpret_cast<float4*>(ws);
        #pragma unroll 4
        for (int idx = tid; idx < WS_FLOATS / 4; idx += 128)
            dst[idx] = src[idx];
    }

    const int iq = tid & 31;          // 32 i-groups
    const int wq = tid >> 5;          // 4 w-groups
    const int i0 = iq * 4;
    const int wbase = wq * 7;

    // ---- Persistent loop over (n,h) pairs ----
    for (int p = blockIdx.x; p < PAIRS; p += gridDim.x) {
        const int n = p / HH;
        const int h = p - n * HH;

        __syncthreads();   // previous GEMM readers done (also orders Phase A on iter 0)

        // ---- Phase B: build T6 tile: t6s[kk*28 + w] = dup(t6[n,l,h+j-1,k,w]) ----
        // t6 = t2(l, w) + t2(32+l, (w-1) mod 28)
        // t2(c, ww) = x[n,c,h',(ww+k-2) mod 28] if 0 <= ww+k-1 < 28 else 0
        {
            int e = tid;
            #pragma unroll 7
            for (int it = 0; it < T6_ELEMS / 128; ++it, e += 128) {  // 63 iters
                const int kk = e / WW;
                const int w  = e - kk * WW;
                const int l  = kk / 9;
                const int r  = kk - l * 9;
                const int j  = r / 3;
                const int k  = r - j * 3;
                const int hp = h + j - 1;
                float v = 0.0f;
                if ((unsigned)hp < (unsigned)HH) {
                    const size_t rowbase = (((size_t)n * CIN + l) * HH + hp) * WW;
                    const int u1 = w + k - 1;
                    if ((unsigned)u1 < (unsigned)WW) {
                        const int c1 = (u1 == 0) ? (WW - 1) : (u1 - 1);
                        v += x[rowbase + c1];
                    }
                    const int w2 = (w == 0) ? (WW - 1) : (w - 1);
                    const int u2 = w2 + k - 1;
                    if ((unsigned)u2 < (unsigned)WW) {
                        const int c2 = (u2 == 0) ? (WW - 1) : (u2 - 1);
                        v += x[rowbase + (size_t)32 * HH * WW + c2];
                    }
                }
                const unsigned ui = __float_as_uint(v);
                t6s[e] = ((unsigned long long)ui << 32) | (unsigned long long)ui;
            }
        }

        __syncthreads();

        // ---- Phase C: GEMM  C[28 x 128] = T6[28 x 288] * W[288 x 128] ----
        unsigned long long acc[7][2];
        #pragma unroll
        for (int t = 0; t < 7; ++t) { acc[t][0] = 0ull; acc[t][1] = 0ull; }

        #pragma unroll 4
        for (int kk = 0; kk < KK; ++kk) {
            const ulonglong2 wv =
                *reinterpret_cast<const ulonglong2*>(&ws[kk * II + i0]); // 4 weights
            const unsigned long long* trow = &t6s[kk * WW + wbase];
            #pragma unroll
            for (int t = 0; t < 7; ++t) {
                const unsigned long long b = trow[t];      // dup f32x2, smem broadcast
                acc[t][0] = fma2(b, wv.x, acc[t][0]);
                acc[t][1] = fma2(b, wv.y, acc[t][1]);
            }
        }

        // ---- Epilogue: out[n, i, h, w], row-major ----
        const size_t obase = (((size_t)n * II + i0) * HH + h) * WW;
        #pragma unroll
        for (int t = 0; t < 7; ++t) {
            const int w = wbase + t;
            out[obase + w]                = ull_lo(acc[t][0]);
            out[obase + 1 * HH * WW + w]  = ull_hi(acc[t][0]);
            out[obase + 2 * HH * WW + w]  = ull_lo(acc[t][1]);
            out[obase + 3 * HH * WW + w]  = ull_hi(acc[t][1]);
        }
    }
}

extern "C" void kernel_launch(void* const* d_in, const int* in_sizes, int n_in,
                              void* d_out, int out_size) {
    const float* x  = (const float*)d_in[0];   // (1024,64,28,28) f32
    const float* Wg = (const float*)d_in[1];   // (32,3,3,128)   f32
    float* out = (float*)d_out;                // (1024,128,28,28) f32

    cudaFuncSetAttribute(shiftconv_kernel,
                         cudaFuncAttributeMaxDynamicSharedMemorySize, SMEM_TOTAL);
    shiftconv_kernel<<<592, 128, SMEM_TOTAL>>>(x, Wg, out);
}